// round 1
// baseline (speedup 1.0000x reference)
#include <cuda_runtime.h>
#include <math.h>

#define S_LEN 2048
#define HID   4096
#define NH    32
#define NKV   8
#define HD    128
#define QKV_OUT 6144   // (32 + 2*8) * 128

// Scratch (device globals: no allocation allowed)
__device__ float g_qkv[S_LEN * QKV_OUT];   // [S, 6144]  q|k|v
__device__ float g_attn[S_LEN * HID];      // [S, 4096]  attention output (head-major)

// ---------------------------------------------------------------------------
// SGEMM:  C[M,N] = A[M,K] @ B[N,K]^T   (A,B,C row-major, all dims % 128 == 0)
// 128x128x8 tile, 256 threads, 8x8 per thread.
// ---------------------------------------------------------------------------
__global__ __launch_bounds__(256) void sgemm_nt(const float* __restrict__ A,
                                                const float* __restrict__ B,
                                                float* __restrict__ C,
                                                int M, int N, int K) {
    __shared__ float As[8][128];
    __shared__ float Bs[8][128];
    const int bm = blockIdx.y * 128;
    const int bn = blockIdx.x * 128;
    const int tid = threadIdx.x;
    const int lr = tid >> 1;          // 0..127 row of tile
    const int lk = (tid & 1) * 4;     // 0 or 4 within BK=8
    const int tx = tid & 15;          // 0..15
    const int ty = tid >> 4;          // 0..15

    float acc[8][8];
#pragma unroll
    for (int i = 0; i < 8; i++)
#pragma unroll
        for (int j = 0; j < 8; j++) acc[i][j] = 0.f;

    const float* Aptr = A + (size_t)(bm + lr) * K + lk;
    const float* Bptr = B + (size_t)(bn + lr) * K + lk;

    for (int k0 = 0; k0 < K; k0 += 8) {
        float4 a = *(const float4*)(Aptr + k0);
        float4 b = *(const float4*)(Bptr + k0);
        As[lk + 0][lr] = a.x; As[lk + 1][lr] = a.y;
        As[lk + 2][lr] = a.z; As[lk + 3][lr] = a.w;
        Bs[lk + 0][lr] = b.x; Bs[lk + 1][lr] = b.y;
        Bs[lk + 2][lr] = b.z; Bs[lk + 3][lr] = b.w;
        __syncthreads();
#pragma unroll
        for (int k = 0; k < 8; k++) {
            float ar[8], br[8];
            *(float4*)&ar[0] = *(const float4*)&As[k][ty * 8];
            *(float4*)&ar[4] = *(const float4*)&As[k][ty * 8 + 4];
            *(float4*)&br[0] = *(const float4*)&Bs[k][tx * 8];
            *(float4*)&br[4] = *(const float4*)&Bs[k][tx * 8 + 4];
#pragma unroll
            for (int i = 0; i < 8; i++)
#pragma unroll
                for (int j = 0; j < 8; j++)
                    acc[i][j] += ar[i] * br[j];
        }
        __syncthreads();
    }

#pragma unroll
    for (int i = 0; i < 8; i++) {
        float4* crow = (float4*)(C + (size_t)(bm + ty * 8 + i) * N + bn + tx * 8);
        crow[0] = make_float4(acc[i][0], acc[i][1], acc[i][2], acc[i][3]);
        crow[1] = make_float4(acc[i][4], acc[i][5], acc[i][6], acc[i][7]);
    }
}

// ---------------------------------------------------------------------------
// RoPE (half-split): applied in-place to the Q (32 heads) and K (8 heads)
// slices of g_qkv.  grid = (S, 40), block = 64 (one thread per rotation pair)
// ---------------------------------------------------------------------------
__global__ void rope_kernel(float* __restrict__ qkv) {
    const int s = blockIdx.x;
    const int h = blockIdx.y;         // 0..39 (32 q heads, then 8 k heads)
    const int i = threadIdx.x;        // 0..63
    const int col = (h < NH) ? h * HD : (NH * HD + (h - NH) * HD);
    float* row = qkv + (size_t)s * QKV_OUT + col;

    double freq = pow(10000.0, -((double)(2 * i) / (double)HD));
    double ang = (double)s * freq;
    float c = (float)cos(ang);
    float sn = (float)sin(ang);
    float x1 = row[i];
    float x2 = row[i + 64];
    row[i]      = x1 * c - x2 * sn;
    row[i + 64] = x1 * sn + x2 * c;
}

// ---------------------------------------------------------------------------
// Flash-style causal attention.
// grid = (32 q-tiles, 32 heads), block = 256.
// Q tile 64x128, K/V tiles 64x128 in smem (stride 132 vs bank conflicts).
// Thread (r = tid/4, cg = tid%4): 16 scores (cols cg*16..+15) and 32
// output accumulators (cols cg + 4*i).
// ---------------------------------------------------------------------------
#define QT 64
#define KT 64
#define PADD 132
#define PADS 68

extern __shared__ float attn_smem[];

__global__ __launch_bounds__(256) void attn_kernel(const float* __restrict__ qkv,
                                                   float* __restrict__ attn_out) {
    float* Qs = attn_smem;            // [64][132]
    float* Ks = Qs + QT * PADD;       // [64][132]
    float* Vs = Ks + KT * PADD;       // [64][132]
    float* Ss = Vs + KT * PADD;       // [64][68]

    const int qt = blockIdx.x;
    const int h  = blockIdx.y;
    const int kvh = h >> 2;           // n_rep = 4
    const int tid = threadIdx.x;
    const int r  = tid >> 2;          // 0..63
    const int cg = tid & 3;           // 0..3
    const float scale = 0.08838834764831845f;  // 1/sqrt(128)

    // Load Q tile (scaled)
    for (int idx = tid; idx < QT * HD / 4; idx += 256) {
        int rr = idx >> 5;            // / 32 float4 per row
        int c4 = (idx & 31) * 4;
        float4 v = *(const float4*)(qkv + (size_t)(qt * QT + rr) * QKV_OUT + h * HD + c4);
        float* dst = Qs + rr * PADD + c4;
        dst[0] = v.x * scale; dst[1] = v.y * scale;
        dst[2] = v.z * scale; dst[3] = v.w * scale;
    }
    __syncthreads();

    float m = -1e30f, l = 0.f;
    float acc[32];
#pragma unroll
    for (int i = 0; i < 32; i++) acc[i] = 0.f;

    const int qi = qt * QT + r;

    for (int kt = 0; kt <= qt; kt++) {
        // Load K and V tiles
        for (int idx = tid; idx < KT * HD / 4; idx += 256) {
            int rr = idx >> 5;
            int c4 = (idx & 31) * 4;
            const float* src = qkv + (size_t)(kt * KT + rr) * QKV_OUT + NH * HD + kvh * HD + c4;
            float4 kv = *(const float4*)src;
            float4 vv = *(const float4*)(src + NKV * HD);
            float* kd = Ks + rr * PADD + c4;
            float* vd = Vs + rr * PADD + c4;
            kd[0] = kv.x; kd[1] = kv.y; kd[2] = kv.z; kd[3] = kv.w;
            vd[0] = vv.x; vd[1] = vv.y; vd[2] = vv.z; vd[3] = vv.w;
        }
        __syncthreads();

        // Scores: 16 per thread
        float sc[16];
        float smax = -1e30f;
        const float4* q4 = (const float4*)(Qs + r * PADD);
#pragma unroll
        for (int cc = 0; cc < 16; cc++) {
            int c = cg * 16 + cc;
            int kj = kt * KT + c;
            const float4* k4 = (const float4*)(Ks + c * PADD);
            float s = 0.f;
#pragma unroll 8
            for (int k = 0; k < HD / 4; k++) {
                float4 a = q4[k], b = k4[k];
                s += a.x * b.x + a.y * b.y + a.z * b.z + a.w * b.w;
            }
            if (kj > qi) s = -1e30f;
            sc[cc] = s;
            smax = fmaxf(smax, s);
        }
        // reduce max across the 4 threads of this row (same warp quad)
        smax = fmaxf(smax, __shfl_xor_sync(0xffffffffu, smax, 1));
        smax = fmaxf(smax, __shfl_xor_sync(0xffffffffu, smax, 2));

        float mnew = fmaxf(m, smax);
        float corr = __expf(m - mnew);
        float psum = 0.f;
#pragma unroll
        for (int cc = 0; cc < 16; cc++) {
            float p = __expf(sc[cc] - mnew);
            Ss[r * PADS + cg * 16 + cc] = p;
            psum += p;
        }
        psum += __shfl_xor_sync(0xffffffffu, psum, 1);
        psum += __shfl_xor_sync(0xffffffffu, psum, 2);
        l = l * corr + psum;
        m = mnew;
#pragma unroll
        for (int i = 0; i < 32; i++) acc[i] *= corr;
        __syncwarp();   // quad-local Ss visibility (writers/readers same warp)

        // O += P @ V     (thread cols: cg + 4*i)
        for (int j = 0; j < KT; j++) {
            float p = Ss[r * PADS + j];
            const float* vrow = Vs + j * PADD + cg;
#pragma unroll
            for (int i = 0; i < 32; i++)
                acc[i] += p * vrow[4 * i];
        }
        __syncthreads();  // protect Ks/Vs/Ss before next tile load
    }

    float inv = 1.f / l;
    float* orow = attn_out + (size_t)qi * HID + h * HD + cg;
#pragma unroll
    for (int i = 0; i < 32; i++)
        orow[4 * i] = acc[i] * inv;
}

// ---------------------------------------------------------------------------
extern "C" void kernel_launch(void* const* d_in, const int* in_sizes, int n_in,
                              void* d_out, int out_size) {
    const float* hidden = (const float*)d_in[0];   // [1, 2048, 4096]
    const float* w_qkv  = (const float*)d_in[1];   // [6144, 4096]
    const float* w_o    = (const float*)d_in[2];   // [4096, 4096]
    float* out = (float*)d_out;                    // [1, 2048, 4096]

    float* qkv_ptr;
    float* attn_ptr;
    cudaGetSymbolAddress((void**)&qkv_ptr, g_qkv);
    cudaGetSymbolAddress((void**)&attn_ptr, g_attn);

    // 1) QKV projection: [2048,6144] = hidden @ w_qkv^T
    sgemm_nt<<<dim3(QKV_OUT / 128, S_LEN / 128), 256>>>(hidden, w_qkv, qkv_ptr,
                                                        S_LEN, QKV_OUT, HID);

    // 2) RoPE on q and k heads
    rope_kernel<<<dim3(S_LEN, NH + NKV), 64>>>(qkv_ptr);

    // 3) Causal GQA attention
    const int attn_smem_bytes = (3 * QT * PADD + QT * PADS) * sizeof(float);
    cudaFuncSetAttribute(attn_kernel, cudaFuncAttributeMaxDynamicSharedMemorySize,
                         attn_smem_bytes);
    attn_kernel<<<dim3(S_LEN / QT, NH), 256, attn_smem_bytes>>>(qkv_ptr, attn_ptr);

    // 4) Output projection: [2048,4096] = attn @ w_o^T
    sgemm_nt<<<dim3(HID / 128, S_LEN / 128), 256>>>(attn_ptr, w_o, out,
                                                    S_LEN, HID, HID);
}

// round 6
// speedup vs baseline: 1.3036x; 1.3036x over previous
#include <cuda_runtime.h>
#include <math.h>

#define S_LEN 2048
#define HID   4096
#define NH    32
#define NKV   8
#define HD    128
#define QKV_OUT 6144   // (32 + 2*8) * 128

// Scratch (device globals: no allocation allowed)
__device__ float g_qkv[S_LEN * QKV_OUT];   // [S, 6144]  q|k|v
__device__ float g_attn[S_LEN * HID];      // [S, 4096]  attention output (head-major)

// ---------------------------------------------------------------------------
// TF32 tensor-core GEMM:  C[M,N] = A[M,K] @ B[N,K]^T
// A row-major [M,K], B row-major [N,K]  -> mma "row.col" (both K-contiguous).
// Block tile 128x128x32, 256 threads = 8 warps, warp tile 64x32.
// Each warp: 4x4 grid of m16n8k8 mma fragments, 4 k-steps per K-tile.
// fp32 -> tf32 conversion with cvt.rna (round-to-nearest) at smem store.
// ---------------------------------------------------------------------------
#define BM 128
#define BN 128
#define BK 32
#define SPAD 36   // BK + 4 padding: fragment LDS banks = 4*(lane/4)+lane%4, conflict-free

__device__ __forceinline__ unsigned f2tf32(float x) {
    unsigned r;
    asm("cvt.rna.tf32.f32 %0, %1;" : "=r"(r) : "f"(x));
    return r;
}

__global__ __launch_bounds__(256, 1) void gemm_tf32_nt(const float* __restrict__ A,
                                                       const float* __restrict__ B,
                                                       float* __restrict__ C,
                                                       int M, int N, int K) {
    __shared__ float As[BM][SPAD];
    __shared__ float Bs[BN][SPAD];

    const int bm = blockIdx.y * BM;
    const int bn = blockIdx.x * BN;
    const int tid = threadIdx.x;
    const int lane = tid & 31;
    const int wid = tid >> 5;
    const int warp_m = (wid >> 2) * 64;   // 0 or 64
    const int warp_n = (wid & 3) * 32;    // 0,32,64,96
    const int lr = lane >> 2;             // 0..7
    const int lc = lane & 3;              // 0..3

    // Global-load mapping: each thread does 4 float4 for A and 4 for B per K-tile
    const int g_r = tid >> 3;             // 0..31
    const int g_c = (tid & 7) * 4;        // 0,4,...,28

    float acc[4][4][4];
#pragma unroll
    for (int i = 0; i < 4; i++)
#pragma unroll
        for (int j = 0; j < 4; j++)
#pragma unroll
            for (int v = 0; v < 4; v++) acc[i][j][v] = 0.f;

    for (int k0 = 0; k0 < K; k0 += BK) {
        // Load A tile [BM x BK] and B tile [BN x BK], convert to tf32 (rna)
#pragma unroll
        for (int i = 0; i < 4; i++) {
            int row = g_r + 32 * i;
            float4 a = *(const float4*)(A + (size_t)(bm + row) * K + k0 + g_c);
            float4 b = *(const float4*)(B + (size_t)(bn + row) * K + k0 + g_c);
            float* ad = &As[row][g_c];
            float* bd = &Bs[row][g_c];
            ad[0] = __uint_as_float(f2tf32(a.x));
            ad[1] = __uint_as_float(f2tf32(a.y));
            ad[2] = __uint_as_float(f2tf32(a.z));
            ad[3] = __uint_as_float(f2tf32(a.w));
            bd[0] = __uint_as_float(f2tf32(b.x));
            bd[1] = __uint_as_float(f2tf32(b.y));
            bd[2] = __uint_as_float(f2tf32(b.z));
            bd[3] = __uint_as_float(f2tf32(b.w));
        }
        __syncthreads();

#pragma unroll
        for (int ks = 0; ks < 4; ks++) {
            const int kb = ks * 8;
            unsigned af[4][4], bf[4][2];
#pragma unroll
            for (int mt = 0; mt < 4; mt++) {
                const int r0 = warp_m + mt * 16 + lr;
                af[mt][0] = __float_as_uint(As[r0][kb + lc]);
                af[mt][1] = __float_as_uint(As[r0 + 8][kb + lc]);
                af[mt][2] = __float_as_uint(As[r0][kb + lc + 4]);
                af[mt][3] = __float_as_uint(As[r0 + 8][kb + lc + 4]);
            }
#pragma unroll
            for (int nt = 0; nt < 4; nt++) {
                const int c0 = warp_n + nt * 8 + lr;
                bf[nt][0] = __float_as_uint(Bs[c0][kb + lc]);
                bf[nt][1] = __float_as_uint(Bs[c0][kb + lc + 4]);
            }
#pragma unroll
            for (int mt = 0; mt < 4; mt++)
#pragma unroll
                for (int nt = 0; nt < 4; nt++) {
                    asm volatile(
                        "mma.sync.aligned.m16n8k8.row.col.f32.tf32.tf32.f32 "
                        "{%0,%1,%2,%3}, {%4,%5,%6,%7}, {%8,%9}, {%0,%1,%2,%3};"
                        : "+f"(acc[mt][nt][0]), "+f"(acc[mt][nt][1]),
                          "+f"(acc[mt][nt][2]), "+f"(acc[mt][nt][3])
                        : "r"(af[mt][0]), "r"(af[mt][1]), "r"(af[mt][2]), "r"(af[mt][3]),
                          "r"(bf[nt][0]), "r"(bf[nt][1]));
                }
        }
        __syncthreads();
    }

    // Epilogue: c0:(lr, lc*2) c1:(lr, lc*2+1) c2/c3: rows +8
#pragma unroll
    for (int mt = 0; mt < 4; mt++) {
#pragma unroll
        for (int nt = 0; nt < 4; nt++) {
            const int r0 = bm + warp_m + mt * 16 + lr;
            const int c0 = bn + warp_n + nt * 8 + lc * 2;
            *(float2*)(C + (size_t)r0 * N + c0) =
                make_float2(acc[mt][nt][0], acc[mt][nt][1]);
            *(float2*)(C + (size_t)(r0 + 8) * N + c0) =
                make_float2(acc[mt][nt][2], acc[mt][nt][3]);
        }
    }
}

// ---------------------------------------------------------------------------
// RoPE (half-split): applied in-place to the Q (32 heads) and K (8 heads)
// slices of g_qkv.  grid = (S, 40), block = 64 (one thread per rotation pair)
// ---------------------------------------------------------------------------
__global__ void rope_kernel(float* __restrict__ qkv) {
    const int s = blockIdx.x;
    const int h = blockIdx.y;         // 0..39 (32 q heads, then 8 k heads)
    const int i = threadIdx.x;        // 0..63
    const int col = (h < NH) ? h * HD : (NH * HD + (h - NH) * HD);
    float* row = qkv + (size_t)s * QKV_OUT + col;

    double freq = pow(10000.0, -((double)(2 * i) / (double)HD));
    double ang = (double)s * freq;
    float c = (float)cos(ang);
    float sn = (float)sin(ang);
    float x1 = row[i];
    float x2 = row[i + 64];
    row[i]      = x1 * c - x2 * sn;
    row[i + 64] = x1 * sn + x2 * c;
}

// ---------------------------------------------------------------------------
// Flash-style causal attention (unchanged from R0 baseline).
// grid = (32 q-tiles, 32 heads), block = 256.
// ---------------------------------------------------------------------------
#define QT 64
#define KT 64
#define PADD 132
#define PADS 68

extern __shared__ float attn_smem[];

__global__ __launch_bounds__(256) void attn_kernel(const float* __restrict__ qkv,
                                                   float* __restrict__ attn_out) {
    float* Qs = attn_smem;            // [64][132]
    float* Ks = Qs + QT * PADD;       // [64][132]
    float* Vs = Ks + KT * PADD;       // [64][132]
    float* Ss = Vs + KT * PADD;       // [64][68]

    const int qt = blockIdx.x;
    const int h  = blockIdx.y;
    const int kvh = h >> 2;           // n_rep = 4
    const int tid = threadIdx.x;
    const int r  = tid >> 2;          // 0..63
    const int cg = tid & 3;           // 0..3
    const float scale = 0.08838834764831845f;  // 1/sqrt(128)

    // Load Q tile (scaled)
    for (int idx = tid; idx < QT * HD / 4; idx += 256) {
        int rr = idx >> 5;            // / 32 float4 per row
        int c4 = (idx & 31) * 4;
        float4 v = *(const float4*)(qkv + (size_t)(qt * QT + rr) * QKV_OUT + h * HD + c4);
        float* dst = Qs + rr * PADD + c4;
        dst[0] = v.x * scale; dst[1] = v.y * scale;
        dst[2] = v.z * scale; dst[3] = v.w * scale;
    }
    __syncthreads();

    float m = -1e30f, l = 0.f;
    float acc[32];
#pragma unroll
    for (int i = 0; i < 32; i++) acc[i] = 0.f;

    const int qi = qt * QT + r;

    for (int kt = 0; kt <= qt; kt++) {
        // Load K and V tiles
        for (int idx = tid; idx < KT * HD / 4; idx += 256) {
            int rr = idx >> 5;
            int c4 = (idx & 31) * 4;
            const float* src = qkv + (size_t)(kt * KT + rr) * QKV_OUT + NH * HD + kvh * HD + c4;
            float4 kv = *(const float4*)src;
            float4 vv = *(const float4*)(src + NKV * HD);
            float* kd = Ks + rr * PADD + c4;
            float* vd = Vs + rr * PADD + c4;
            kd[0] = kv.x; kd[1] = kv.y; kd[2] = kv.z; kd[3] = kv.w;
            vd[0] = vv.x; vd[1] = vv.y; vd[2] = vv.z; vd[3] = vv.w;
        }
        __syncthreads();

        // Scores: 16 per thread
        float sc[16];
        float smax = -1e30f;
        const float4* q4 = (const float4*)(Qs + r * PADD);
#pragma unroll
        for (int cc = 0; cc < 16; cc++) {
            int c = cg * 16 + cc;
            int kj = kt * KT + c;
            const float4* k4 = (const float4*)(Ks + c * PADD);
            float s = 0.f;
#pragma unroll 8
            for (int k = 0; k < HD / 4; k++) {
                float4 a = q4[k], b = k4[k];
                s += a.x * b.x + a.y * b.y + a.z * b.z + a.w * b.w;
            }
            if (kj > qi) s = -1e30f;
            sc[cc] = s;
            smax = fmaxf(smax, s);
        }
        // reduce max across the 4 threads of this row (same warp quad)
        smax = fmaxf(smax, __shfl_xor_sync(0xffffffffu, smax, 1));
        smax = fmaxf(smax, __shfl_xor_sync(0xffffffffu, smax, 2));

        float mnew = fmaxf(m, smax);
        float corr = __expf(m - mnew);
        float psum = 0.f;
#pragma unroll
        for (int cc = 0; cc < 16; cc++) {
            float p = __expf(sc[cc] - mnew);
            Ss[r * PADS + cg * 16 + cc] = p;
            psum += p;
        }
        psum += __shfl_xor_sync(0xffffffffu, psum, 1);
        psum += __shfl_xor_sync(0xffffffffu, psum, 2);
        l = l * corr + psum;
        m = mnew;
#pragma unroll
        for (int i = 0; i < 32; i++) acc[i] *= corr;
        __syncwarp();   // quad-local Ss visibility (writers/readers same warp)

        // O += P @ V     (thread cols: cg + 4*i)
        for (int j = 0; j < KT; j++) {
            float p = Ss[r * PADS + j];
            const float* vrow = Vs + j * PADD + cg;
#pragma unroll
            for (int i = 0; i < 32; i++)
                acc[i] += p * vrow[4 * i];
        }
        __syncthreads();  // protect Ks/Vs/Ss before next tile load
    }

    float inv = 1.f / l;
    float* orow = attn_out + (size_t)qi * HID + h * HD + cg;
#pragma unroll
    for (int i = 0; i < 32; i++)
        orow[4 * i] = acc[i] * inv;
}

// ---------------------------------------------------------------------------
extern "C" void kernel_launch(void* const* d_in, const int* in_sizes, int n_in,
                              void* d_out, int out_size) {
    const float* hidden = (const float*)d_in[0];   // [1, 2048, 4096]
    const float* w_qkv  = (const float*)d_in[1];   // [6144, 4096]
    const float* w_o    = (const float*)d_in[2];   // [4096, 4096]
    float* out = (float*)d_out;                    // [1, 2048, 4096]

    float* qkv_ptr;
    float* attn_ptr;
    cudaGetSymbolAddress((void**)&qkv_ptr, g_qkv);
    cudaGetSymbolAddress((void**)&attn_ptr, g_attn);

    // 1) QKV projection: [2048,6144] = hidden @ w_qkv^T   (tf32 tensor cores)
    gemm_tf32_nt<<<dim3(QKV_OUT / BN, S_LEN / BM), 256>>>(hidden, w_qkv, qkv_ptr,
                                                          S_LEN, QKV_OUT, HID);

    // 2) RoPE on q and k heads
    rope_kernel<<<dim3(S_LEN, NH + NKV), 64>>>(qkv_ptr);

    // 3) Causal GQA attention
    const int attn_smem_bytes = (3 * QT * PADD + QT * PADS) * sizeof(float);
    cudaFuncSetAttribute(attn_kernel, cudaFuncAttributeMaxDynamicSharedMemorySize,
                         attn_smem_bytes);
    attn_kernel<<<dim3(S_LEN / QT, NH), 256, attn_smem_bytes>>>(qkv_ptr, attn_ptr);

    // 4) Output projection: [2048,4096] = attn @ w_o^T    (tf32 tensor cores)
    gemm_tf32_nt<<<dim3(HID / BN, S_LEN / BM), 256>>>(attn_ptr, w_o, out,
                                                      S_LEN, HID, HID);
}